// round 16
// baseline (speedup 1.0000x reference)
#include <cuda_runtime.h>
#include <cuda_fp16.h>
#include <math.h>

#define NPOS 392
#define KK   288          // K*K*IN_CAPS
#define OC   32
#define PS   16
#define OSZ  512          // OC*PS
#define CEPS 1e-8f
#define LN2PI 1.8378770664093453f
#define NT   512          // 16 warps; 2 CTAs/SM

// vote scratch (fp16): 392 * 288 * 512 * 2B = 115.6 MB
__device__ __half g_votes[(size_t)NPOS * KK * OSZ];

extern __shared__ float smem[];

// ---- packed fp32x2 helpers (B300 FFMA2 path; full fp32 precision) ----
typedef unsigned long long u64;
__device__ __forceinline__ u64 f2pack(float lo, float hi) {
    u64 r;
    asm("mov.b64 %0, {%1, %2};" : "=l"(r) : "f"(lo), "f"(hi));
    return r;
}
__device__ __forceinline__ void f2unpack(u64 v, float& lo, float& hi) {
    asm("mov.b64 {%0, %1}, %2;" : "=f"(lo), "=f"(hi) : "l"(v));
}
__device__ __forceinline__ u64 f2mul(u64 a, u64 b) {
    u64 d;
    asm("mul.rn.f32x2 %0, %1, %2;" : "=l"(d) : "l"(a), "l"(b));
    return d;
}
__device__ __forceinline__ u64 f2add(u64 a, u64 b) {
    u64 d;
    asm("add.rn.f32x2 %0, %1, %2;" : "=l"(d) : "l"(a), "l"(b));
    return d;
}
__device__ __forceinline__ u64 f2fma(u64 a, u64 b, u64 c) {
    u64 d;
    asm("fma.rn.f32x2 %0, %1, %2, %3;" : "=l"(d) : "l"(a), "l"(b), "l"(c));
    return d;
}

// Finalize mean/var/act/C from raw sums; zeroes Mb/Qb after reading (same
// thread reads-then-writes; barrier follows outside -> race-free).
__device__ __forceinline__ void stats_phase(
    int tid, float* Mb, float* Qb,
    const float* rsArr, float rsUni, float lam,
    float* sMean, float* sIv, float* sAct, float* sC,
    const float* __restrict__ beta_u, const float* __restrict__ beta_a)
{
    if (tid < 256) {
        const int o  = tid >> 3;
        const int sp = tid & 7;
        float rs  = rsArr ? rsArr[o] : rsUni;
        float irs = 1.f/(rs + CEPS);
        float s1  = rs/(rs + CEPS);
        float M0 = Mb[o*16 + 2*sp]   * irs;
        float M1 = Mb[o*16 + 2*sp+1] * irs;
        float Q0 = Qb[o*16 + 2*sp]   * irs;
        float Q1 = Qb[o*16 + 2*sp+1] * irs;
        Mb[o*16 + 2*sp] = 0.f; Mb[o*16 + 2*sp+1] = 0.f;
        Qb[o*16 + 2*sp] = 0.f; Qb[o*16 + 2*sp+1] = 0.f;
        // sum r*(v-mean)^2 = Q - mean^2*(2 - S1)   (exact EPS algebra)
        float v0 = fmaxf(Q0 - M0*M0*(2.f - s1), 0.f) + CEPS;
        float v1 = fmaxf(Q1 - M1*M1*(2.f - s1), 0.f) + CEPS;
        sMean[o*17 + 2*sp]   = M0;
        sMean[o*17 + 2*sp+1] = M1;
        sIv[o*17 + 2*sp]     = 0.5f/v0;
        sIv[o*17 + 2*sp+1]   = 0.5f/v1;
        float sl = 0.5f*(__logf(v0) + __logf(v1));
        #pragma unroll
        for (int off = 1; off < 8; off <<= 1)
            sl += __shfl_xor_sync(0xffffffffu, sl, off);
        if (sp == 0) {
            float cost = (16.f*beta_u[o] + sl) * rs;
            float z = lam * (beta_a[o] - cost);
            float a = 1.f/(1.f + __expf(-z));
            sAct[o] = a;
            sC[o]   = __logf(a) - sl - 8.f*LN2PI;
        }
    }
}

__global__ __launch_bounds__(NT, 2)
void convcaps_kernel(const float* __restrict__ x,
                     const float* __restrict__ wts,
                     const float* __restrict__ beta_u,
                     const float* __restrict__ beta_a,
                     float* __restrict__ out)
{
    const int n    = blockIdx.x;
    const int tid  = threadIdx.x;
    const int lane = tid & 31;
    const int wid  = tid >> 5;

    // ---- smem carve (~64 KB) ----
    float* sP    = smem;            // 4608  poses [k][s]
    float* sCk   = sP + KK*PS;      // 288   ck = a/(a+eps)
    float* sR    = sCk + KK;        // 9216  r_hat [k][o]
    float* sM    = sR + KK*OC;      // 512   raw M sums
    float* sQ    = sM + 512;        // 512   raw Q sums
    float* sMean = sQ + 512;        // 544   [o*17+s]
    float* sIv   = sMean + 544;     // 544
    float* sRs1  = sIv + 544;       // 32
    float* sRs2  = sRs1 + 32;       // 32
    float* sAct  = sRs2 + 32;       // 32
    float* sC    = sAct + 32;       // 32
    float* sCkS  = sC + 32;         // 1

    // ---- zero accumulators ----
    for (int i = tid; i < 1024; i += NT) sM[i] = 0.f;   // sM+sQ contiguous
    if (tid < 64) sRs1[tid] = 0.f;                      // sRs1+sRs2 contiguous
    if (tid == 64) *sCkS = 0.f;
    __syncthreads();

    // ---- Phase 0: gather input tile (reference reshape semantics) ----
    const int b = n / 49;
    const int m = n - b*49;
    for (int idx = tid; idx < 9*544; idx += NT) {
        int j   = idx / 544;
        int c   = idx - j*544;
        int t9  = 9*m + j;
        int khw = t9 / 49;
        int oyx = t9 - khw*49;
        int oy  = oyx / 7;
        int ox  = oyx - oy*7;
        int kh  = khw / 3;
        int kw  = khw - kh*3;
        int h   = 2*oy + kh;
        int w   = 2*ox + kw;
        float v = x[(size_t)(((b*16 + h)*16) + w)*544 + c];
        if (c < 512) {
            sP[j*512 + c] = v;
        } else {
            float ck = v / (v + CEPS);
            sCk[j*32 + (c - 512)] = ck;
            atomicAdd(sCkS, ck);
        }
    }
    __syncthreads();

    // ---- Phase 1: vote gen, packed f32x2 matmul ----
    __half* vbase = g_votes + (size_t)n * (KK*OSZ);
    for (int pair = tid; pair < KK*OC; pair += NT) {
        int k = pair >> 5;
        const float* p = sP + k*PS;
        const float4* wv4 = (const float4*)(wts + (size_t)pair*16);
        u64 wp[8];
        #pragma unroll
        for (int qi = 0; qi < 4; ++qi) {
            float4 t = wv4[qi];
            wp[2*qi]   = f2pack(t.x, t.y);
            wp[2*qi+1] = f2pack(t.z, t.w);
        }
        __half2 hh[8];
        #pragma unroll
        for (int i = 0; i < 4; ++i) {
            u64 P0 = f2pack(p[i*4+0], p[i*4+0]);
            u64 P1 = f2pack(p[i*4+1], p[i*4+1]);
            u64 P2 = f2pack(p[i*4+2], p[i*4+2]);
            u64 P3 = f2pack(p[i*4+3], p[i*4+3]);
            u64 r01 = f2mul(P0, wp[0]);
            r01 = f2fma(P1, wp[2], r01);
            r01 = f2fma(P2, wp[4], r01);
            r01 = f2fma(P3, wp[6], r01);
            u64 r23 = f2mul(P0, wp[1]);
            r23 = f2fma(P1, wp[3], r23);
            r23 = f2fma(P2, wp[5], r23);
            r23 = f2fma(P3, wp[7], r23);
            float r0, r1, r2, r3;
            f2unpack(r01, r0, r1);
            f2unpack(r23, r2, r3);
            hh[2*i+0] = __floats2half2_rn(r0, r1);
            hh[2*i+1] = __floats2half2_rn(r2, r3);
        }
        uint4* dst = (uint4*)(vbase + (size_t)pair*16);
        uint4 u0, u1;
        u0.x = *(unsigned*)&hh[0]; u0.y = *(unsigned*)&hh[1];
        u0.z = *(unsigned*)&hh[2]; u0.w = *(unsigned*)&hh[3];
        u1.x = *(unsigned*)&hh[4]; u1.y = *(unsigned*)&hh[5];
        u1.z = *(unsigned*)&hh[6]; u1.w = *(unsigned*)&hh[7];
        dst[0] = u0; dst[1] = u1;
    }
    __syncthreads();

    // ---- m-passes + e-passes, 3 EM iterations ----
    #pragma unroll 1
    for (int it = 0; it <= 2; ++it) {
        // (m) accumulate raw M/Q sums over k (uint2 loads, packed f32x2 math)
        {
            const int kq = tid >> 7;
            const int ix = tid & 127;
            const int o  = ix >> 2;
            const int sb = 4*(ix & 3);
            const uint2* vp = (const uint2*)((const char*)vbase + ix*8);
            u64 m01 = 0ull, m23 = 0ull, q01 = 0ull, q23 = 0ull;
            const int k0 = kq * 72;
            if (it == 0) {
                #pragma unroll 8
                for (int k = k0; k < k0 + 72; ++k) {
                    uint2 u = vp[(size_t)k*128];
                    float2 fa = __half22float2(*(__half2*)&u.x);
                    float2 fb = __half22float2(*(__half2*)&u.y);
                    float r = sCk[k] * 0.03125f;
                    u64 r2 = f2pack(r, r);
                    u64 va = f2pack(fa.x, fa.y);
                    u64 vb = f2pack(fb.x, fb.y);
                    u64 rva = f2mul(r2, va);
                    u64 rvb = f2mul(r2, vb);
                    m01 = f2add(m01, rva);
                    m23 = f2add(m23, rvb);
                    q01 = f2fma(rva, va, q01);
                    q23 = f2fma(rvb, vb, q23);
                }
            } else {
                const float* rp0 = sR + o;
                #pragma unroll 8
                for (int k = k0; k < k0 + 72; ++k) {
                    uint2 u = vp[(size_t)k*128];
                    float2 fa = __half22float2(*(__half2*)&u.x);
                    float2 fb = __half22float2(*(__half2*)&u.y);
                    float r = rp0[k*32];
                    u64 r2 = f2pack(r, r);
                    u64 va = f2pack(fa.x, fa.y);
                    u64 vb = f2pack(fb.x, fb.y);
                    u64 rva = f2mul(r2, va);
                    u64 rvb = f2mul(r2, vb);
                    m01 = f2add(m01, rva);
                    m23 = f2add(m23, rvb);
                    q01 = f2fma(rva, va, q01);
                    q23 = f2fma(rvb, vb, q23);
                }
            }
            float m0, m1, m2, m3, q0, q1, q2, q3;
            f2unpack(m01, m0, m1); f2unpack(m23, m2, m3);
            f2unpack(q01, q0, q1); f2unpack(q23, q2, q3);
            atomicAdd(&sM[o*16 + sb + 0], m0);
            atomicAdd(&sM[o*16 + sb + 1], m1);
            atomicAdd(&sM[o*16 + sb + 2], m2);
            atomicAdd(&sM[o*16 + sb + 3], m3);
            atomicAdd(&sQ[o*16 + sb + 0], q0);
            atomicAdd(&sQ[o*16 + sb + 1], q1);
            atomicAdd(&sQ[o*16 + sb + 2], q2);
            atomicAdd(&sQ[o*16 + sb + 3], q3);
        }
        __syncthreads();

        // (stats) finalize; zeroes sM/sQ for the next m-pass
        {
            const float* rsArr = (it == 0) ? nullptr : ((it == 1) ? sRs1 : sRs2);
            const float rsUni  = (it == 0) ? (*sCkS)*0.03125f : 0.f;
            const float lam    = 0.0011f + 0.0001f*it;
            stats_phase(tid, sM, sQ, rsArr, rsUni, lam,
                        sMean, sIv, sAct, sC, beta_u, beta_a);
        }
        __syncthreads();

        if (it == 2) break;

        // (e) r_hat = softmax_o(lnap) * ck -> sR; 2-way k-interleave +
        // software-pipelined vote prefetch (next iteration's LDGs issue
        // before this iteration's compute/shuffle chain). half2 stats.
        // No max-subtraction (softmax shift-invariance; lnap in fp32 range).
        {
            float* rs = (it == 0) ? sRs1 : sRs2;
            __half2 mh[8], ivh[8];
            #pragma unroll
            for (int h = 0; h < 8; ++h) {
                mh[h]  = __floats2half2_rn(sMean[lane*17 + 2*h], sMean[lane*17 + 2*h+1]);
                ivh[h] = __floats2half2_rn(sIv[lane*17 + 2*h],   sIv[lane*17 + 2*h+1]);
            }
            const float Co = sC[lane];
            const uint4* vr = (const uint4*)vbase;
            float racc = 0.f;
            // preload i=0
            size_t roA = (size_t)(wid*32 + lane)*2;
            size_t roB = (size_t)((wid + 16)*32 + lane)*2;
            uint4 a0 = vr[roA], a1 = vr[roA + 1];
            uint4 b0 = vr[roB], b1 = vr[roB + 1];
            #pragma unroll 1
            for (int i = 0; i < 9; ++i) {
                const int ka = wid + 32*i;
                const int kb = ka + 16;
                // prefetch next iteration (clamped at the tail; redundant load)
                const int kn = (i < 8) ? ka + 32 : ka;
                size_t rnA = (size_t)(kn*32 + lane)*2;
                size_t rnB = (size_t)((kn + 16)*32 + lane)*2;
                uint4 na0 = vr[rnA], na1 = vr[rnA + 1];
                uint4 nb0 = vr[rnB], nb1 = vr[rnB + 1];
                // compute with current buffers
                float accA = 0.f, accB = 0.f;
                #pragma unroll
                for (int h = 0; h < 8; ++h) {
                    float2 mm = __half22float2(mh[h]);
                    float2 iv = __half22float2(ivh[h]);
                    unsigned ua = (h < 4) ? (&a0.x)[h] : (&a1.x)[h-4];
                    float2 fa = __half22float2(*(__half2*)&ua);
                    float dA0 = fa.x - mm.x, dA1 = fa.y - mm.y;
                    accA += dA0*dA0*iv.x + dA1*dA1*iv.y;
                    unsigned ub = (h < 4) ? (&b0.x)[h] : (&b1.x)[h-4];
                    float2 fb = __half22float2(*(__half2*)&ub);
                    float dB0 = fb.x - mm.x, dB1 = fb.y - mm.y;
                    accB += dB0*dB0*iv.x + dB1*dB1*iv.y;
                }
                float eA = __expf(Co - accA);
                float eB = __expf(Co - accB);
                float sA = eA, sB = eB;
                #pragma unroll
                for (int off = 16; off; off >>= 1) {
                    sA += __shfl_xor_sync(0xffffffffu, sA, off);
                    sB += __shfl_xor_sync(0xffffffffu, sB, off);
                }
                float rA = __fdividef(eA, sA) * sCk[ka];  // exact r*a, o-normalized
                float rB = __fdividef(eB, sB) * sCk[kb];
                sR[ka*32 + lane] = rA;
                sR[kb*32 + lane] = rB;
                racc += rA + rB;
                a0 = na0; a1 = na1; b0 = nb0; b1 = nb1;
            }
            atomicAdd(&rs[lane], racc);
        }
        __syncthreads();
    }

    // ---- output: [n, 544] = concat(mean[32*16], act[32]) ----
    {
        int o = tid >> 4, s = tid & 15;
        out[(size_t)n*544 + tid] = sMean[o*17 + s];
        if (tid < 32)
            out[(size_t)n*544 + 512 + tid] = sAct[tid];
    }
}

extern "C" void kernel_launch(void* const* d_in, const int* in_sizes, int n_in,
                              void* d_out, int out_size)
{
    const float* x  = (const float*)d_in[0];
    const float* w  = (const float*)d_in[1];
    const float* bu = (const float*)d_in[2];
    const float* ba = (const float*)d_in[3];
    float* out = (float*)d_out;

    // 80 KB request pins occupancy at exactly 2 CTAs/SM (L2-resident vote wave)
    const int smem_bytes = 81920;
    cudaFuncSetAttribute(convcaps_kernel,
                         cudaFuncAttributeMaxDynamicSharedMemorySize, smem_bytes);
    convcaps_kernel<<<NPOS, NT, smem_bytes>>>(x, w, bu, ba, out);
}

// round 17
// speedup vs baseline: 1.0760x; 1.0760x over previous
#include <cuda_runtime.h>
#include <cuda_fp16.h>
#include <math.h>

#define NPOS 392
#define KK   288          // K*K*IN_CAPS
#define OC   32
#define PS   16
#define OSZ  512          // OC*PS
#define CEPS 1e-8f
#define LN2PI 1.8378770664093453f
#define NT   512          // 16 warps; 2 CTAs/SM

// vote scratch (fp16): 392 * 288 * 512 * 2B = 115.6 MB
__device__ __half g_votes[(size_t)NPOS * KK * OSZ];

extern __shared__ float smem[];

// ---- packed fp32x2 helpers (B300 FFMA2 path; full fp32 precision) ----
typedef unsigned long long u64;
__device__ __forceinline__ u64 f2pack(float lo, float hi) {
    u64 r;
    asm("mov.b64 %0, {%1, %2};" : "=l"(r) : "f"(lo), "f"(hi));
    return r;
}
__device__ __forceinline__ void f2unpack(u64 v, float& lo, float& hi) {
    asm("mov.b64 {%0, %1}, %2;" : "=f"(lo), "=f"(hi) : "l"(v));
}
__device__ __forceinline__ u64 f2mul(u64 a, u64 b) {
    u64 d;
    asm("mul.rn.f32x2 %0, %1, %2;" : "=l"(d) : "l"(a), "l"(b));
    return d;
}
__device__ __forceinline__ u64 f2add(u64 a, u64 b) {
    u64 d;
    asm("add.rn.f32x2 %0, %1, %2;" : "=l"(d) : "l"(a), "l"(b));
    return d;
}
__device__ __forceinline__ u64 f2fma(u64 a, u64 b, u64 c) {
    u64 d;
    asm("fma.rn.f32x2 %0, %1, %2, %3;" : "=l"(d) : "l"(a), "l"(b), "l"(c));
    return d;
}

// Finalize mean/var/act/C from raw sums; zeroes Mb/Qb after reading (same
// thread reads-then-writes; barrier follows outside -> race-free).
__device__ __forceinline__ void stats_phase(
    int tid, float* Mb, float* Qb,
    const float* rsArr, float rsUni, float lam,
    float* sMean, float* sIv, float* sAct, float* sC,
    const float* __restrict__ beta_u, const float* __restrict__ beta_a)
{
    if (tid < 256) {
        const int o  = tid >> 3;
        const int sp = tid & 7;
        float rs  = rsArr ? rsArr[o] : rsUni;
        float irs = 1.f/(rs + CEPS);
        float s1  = rs/(rs + CEPS);
        float M0 = Mb[o*16 + 2*sp]   * irs;
        float M1 = Mb[o*16 + 2*sp+1] * irs;
        float Q0 = Qb[o*16 + 2*sp]   * irs;
        float Q1 = Qb[o*16 + 2*sp+1] * irs;
        Mb[o*16 + 2*sp] = 0.f; Mb[o*16 + 2*sp+1] = 0.f;
        Qb[o*16 + 2*sp] = 0.f; Qb[o*16 + 2*sp+1] = 0.f;
        // sum r*(v-mean)^2 = Q - mean^2*(2 - S1)   (exact EPS algebra)
        float v0 = fmaxf(Q0 - M0*M0*(2.f - s1), 0.f) + CEPS;
        float v1 = fmaxf(Q1 - M1*M1*(2.f - s1), 0.f) + CEPS;
        sMean[o*17 + 2*sp]   = M0;
        sMean[o*17 + 2*sp+1] = M1;
        sIv[o*17 + 2*sp]     = 0.5f/v0;
        sIv[o*17 + 2*sp+1]   = 0.5f/v1;
        float sl = 0.5f*(__logf(v0) + __logf(v1));
        #pragma unroll
        for (int off = 1; off < 8; off <<= 1)
            sl += __shfl_xor_sync(0xffffffffu, sl, off);
        if (sp == 0) {
            float cost = (16.f*beta_u[o] + sl) * rs;
            float z = lam * (beta_a[o] - cost);
            float a = 1.f/(1.f + __expf(-z));
            sAct[o] = a;
            sC[o]   = __logf(a) - sl - 8.f*LN2PI;
        }
    }
}

__global__ __launch_bounds__(NT, 2)
void convcaps_kernel(const float* __restrict__ x,
                     const float* __restrict__ wts,
                     const float* __restrict__ beta_u,
                     const float* __restrict__ beta_a,
                     float* __restrict__ out)
{
    const int n    = blockIdx.x;
    const int tid  = threadIdx.x;
    const int lane = tid & 31;
    const int wid  = tid >> 5;

    // ---- smem carve (~64 KB) ----
    float* sP    = smem;            // 4608  poses [k][s]
    float* sCk   = sP + KK*PS;      // 288   ck = a/(a+eps)
    float* sR    = sCk + KK;        // 9216  r_hat [k][o]
    float* sM    = sR + KK*OC;      // 512   raw M sums
    float* sQ    = sM + 512;        // 512   raw Q sums
    float* sMean = sQ + 512;        // 544   [o*17+s]
    float* sIv   = sMean + 544;     // 544
    float* sRs1  = sIv + 544;       // 32
    float* sRs2  = sRs1 + 32;       // 32
    float* sAct  = sRs2 + 32;       // 32
    float* sC    = sAct + 32;       // 32
    float* sCkS  = sC + 32;         // 1

    // ---- zero accumulators ----
    for (int i = tid; i < 1024; i += NT) sM[i] = 0.f;   // sM+sQ contiguous
    if (tid < 64) sRs1[tid] = 0.f;                      // sRs1+sRs2 contiguous
    if (tid == 64) *sCkS = 0.f;
    __syncthreads();

    // ---- Phase 0: gather input tile (reference reshape semantics) ----
    const int b = n / 49;
    const int m = n - b*49;
    for (int idx = tid; idx < 9*544; idx += NT) {
        int j   = idx / 544;
        int c   = idx - j*544;
        int t9  = 9*m + j;
        int khw = t9 / 49;
        int oyx = t9 - khw*49;
        int oy  = oyx / 7;
        int ox  = oyx - oy*7;
        int kh  = khw / 3;
        int kw  = khw - kh*3;
        int h   = 2*oy + kh;
        int w   = 2*ox + kw;
        float v = x[(size_t)(((b*16 + h)*16) + w)*544 + c];
        if (c < 512) {
            sP[j*512 + c] = v;
        } else {
            float ck = v / (v + CEPS);
            sCk[j*32 + (c - 512)] = ck;
            atomicAdd(sCkS, ck);
        }
    }
    __syncthreads();

    // ---- Phase 1: vote gen, packed f32x2 matmul; float4 pose loads ----
    __half* vbase = g_votes + (size_t)n * (KK*OSZ);
    for (int pair = tid; pair < KK*OC; pair += NT) {
        int k = pair >> 5;
        const float4* p4 = (const float4*)(sP + k*PS);
        const float4* wv4 = (const float4*)(wts + (size_t)pair*16);
        u64 wp[8];
        #pragma unroll
        for (int qi = 0; qi < 4; ++qi) {
            float4 t = wv4[qi];
            wp[2*qi]   = f2pack(t.x, t.y);
            wp[2*qi+1] = f2pack(t.z, t.w);
        }
        __half2 hh[8];
        #pragma unroll
        for (int i = 0; i < 4; ++i) {
            float4 Pv = p4[i];                 // one LDS.128 per row
            u64 P0 = f2pack(Pv.x, Pv.x);
            u64 P1 = f2pack(Pv.y, Pv.y);
            u64 P2 = f2pack(Pv.z, Pv.z);
            u64 P3 = f2pack(Pv.w, Pv.w);
            u64 r01 = f2mul(P0, wp[0]);
            r01 = f2fma(P1, wp[2], r01);
            r01 = f2fma(P2, wp[4], r01);
            r01 = f2fma(P3, wp[6], r01);
            u64 r23 = f2mul(P0, wp[1]);
            r23 = f2fma(P1, wp[3], r23);
            r23 = f2fma(P2, wp[5], r23);
            r23 = f2fma(P3, wp[7], r23);
            float r0, r1, r2, r3;
            f2unpack(r01, r0, r1);
            f2unpack(r23, r2, r3);
            hh[2*i+0] = __floats2half2_rn(r0, r1);
            hh[2*i+1] = __floats2half2_rn(r2, r3);
        }
        uint4* dst = (uint4*)(vbase + (size_t)pair*16);
        uint4 u0, u1;
        u0.x = *(unsigned*)&hh[0]; u0.y = *(unsigned*)&hh[1];
        u0.z = *(unsigned*)&hh[2]; u0.w = *(unsigned*)&hh[3];
        u1.x = *(unsigned*)&hh[4]; u1.y = *(unsigned*)&hh[5];
        u1.z = *(unsigned*)&hh[6]; u1.w = *(unsigned*)&hh[7];
        dst[0] = u0; dst[1] = u1;
    }
    __syncthreads();

    // ---- m-passes + e-passes, 3 EM iterations ----
    #pragma unroll 1
    for (int it = 0; it <= 2; ++it) {
        // (m) accumulate raw M/Q sums over k (uint2 loads, packed f32x2 math)
        {
            const int kq = tid >> 7;
            const int ix = tid & 127;
            const int o  = ix >> 2;
            const int sb = 4*(ix & 3);
            const uint2* vp = (const uint2*)((const char*)vbase + ix*8);
            u64 m01 = 0ull, m23 = 0ull, q01 = 0ull, q23 = 0ull;
            const int k0 = kq * 72;
            if (it == 0) {
                #pragma unroll 8
                for (int k = k0; k < k0 + 72; ++k) {
                    uint2 u = vp[(size_t)k*128];
                    float2 fa = __half22float2(*(__half2*)&u.x);
                    float2 fb = __half22float2(*(__half2*)&u.y);
                    float r = sCk[k] * 0.03125f;
                    u64 r2 = f2pack(r, r);
                    u64 va = f2pack(fa.x, fa.y);
                    u64 vb = f2pack(fb.x, fb.y);
                    u64 rva = f2mul(r2, va);
                    u64 rvb = f2mul(r2, vb);
                    m01 = f2add(m01, rva);
                    m23 = f2add(m23, rvb);
                    q01 = f2fma(rva, va, q01);
                    q23 = f2fma(rvb, vb, q23);
                }
            } else {
                const float* rp0 = sR + o;
                #pragma unroll 8
                for (int k = k0; k < k0 + 72; ++k) {
                    uint2 u = vp[(size_t)k*128];
                    float2 fa = __half22float2(*(__half2*)&u.x);
                    float2 fb = __half22float2(*(__half2*)&u.y);
                    float r = rp0[k*32];
                    u64 r2 = f2pack(r, r);
                    u64 va = f2pack(fa.x, fa.y);
                    u64 vb = f2pack(fb.x, fb.y);
                    u64 rva = f2mul(r2, va);
                    u64 rvb = f2mul(r2, vb);
                    m01 = f2add(m01, rva);
                    m23 = f2add(m23, rvb);
                    q01 = f2fma(rva, va, q01);
                    q23 = f2fma(rvb, vb, q23);
                }
            }
            float m0, m1, m2, m3, q0, q1, q2, q3;
            f2unpack(m01, m0, m1); f2unpack(m23, m2, m3);
            f2unpack(q01, q0, q1); f2unpack(q23, q2, q3);
            atomicAdd(&sM[o*16 + sb + 0], m0);
            atomicAdd(&sM[o*16 + sb + 1], m1);
            atomicAdd(&sM[o*16 + sb + 2], m2);
            atomicAdd(&sM[o*16 + sb + 3], m3);
            atomicAdd(&sQ[o*16 + sb + 0], q0);
            atomicAdd(&sQ[o*16 + sb + 1], q1);
            atomicAdd(&sQ[o*16 + sb + 2], q2);
            atomicAdd(&sQ[o*16 + sb + 3], q3);
        }
        __syncthreads();

        // (stats) finalize; zeroes sM/sQ for the next m-pass
        {
            const float* rsArr = (it == 0) ? nullptr : ((it == 1) ? sRs1 : sRs2);
            const float rsUni  = (it == 0) ? (*sCkS)*0.03125f : 0.f;
            const float lam    = 0.0011f + 0.0001f*it;
            stats_phase(tid, sM, sQ, rsArr, rsUni, lam,
                        sMean, sIv, sAct, sC, beta_u, beta_a);
        }
        __syncthreads();

        if (it == 2) break;

        // (e) r_hat = softmax_o(lnap) * ck -> sR; 2-way k-interleave,
        // packed f32x2 distance math with pre-negated fp32 means.
        // No max-subtraction (softmax shift-invariance; lnap in fp32 range).
        {
            float* rs = (it == 0) ? sRs1 : sRs2;
            u64 nm[8], iv2[8];
            #pragma unroll
            for (int h = 0; h < 8; ++h) {
                nm[h]  = f2pack(-sMean[lane*17 + 2*h], -sMean[lane*17 + 2*h+1]);
                iv2[h] = f2pack(sIv[lane*17 + 2*h],    sIv[lane*17 + 2*h+1]);
            }
            const float Co = sC[lane];
            const uint4* vr = (const uint4*)vbase;
            float racc = 0.f;
            #pragma unroll 1
            for (int i = 0; i < 9; ++i) {
                const int ka = wid + 32*i;
                const int kb = ka + 16;
                float ckA = sCk[ka];           // hoisted: LDS overlaps LDGs
                float ckB = sCk[kb];
                uint4 a0 = vr[(size_t)(ka*32 + lane)*2];
                uint4 a1 = vr[(size_t)(ka*32 + lane)*2 + 1];
                uint4 b0 = vr[(size_t)(kb*32 + lane)*2];
                uint4 b1 = vr[(size_t)(kb*32 + lane)*2 + 1];
                u64 accA2 = 0ull, accB2 = 0ull;
                #pragma unroll
                for (int h = 0; h < 8; ++h) {
                    unsigned ua = (h < 4) ? (&a0.x)[h] : (&a1.x)[h-4];
                    float2 fa = __half22float2(*(__half2*)&ua);
                    u64 dA = f2add(f2pack(fa.x, fa.y), nm[h]);
                    accA2 = f2fma(f2mul(dA, dA), iv2[h], accA2);
                    unsigned ub = (h < 4) ? (&b0.x)[h] : (&b1.x)[h-4];
                    float2 fb = __half22float2(*(__half2*)&ub);
                    u64 dB = f2add(f2pack(fb.x, fb.y), nm[h]);
                    accB2 = f2fma(f2mul(dB, dB), iv2[h], accB2);
                }
                float aLo, aHi, bLo, bHi;
                f2unpack(accA2, aLo, aHi);
                f2unpack(accB2, bLo, bHi);
                float eA = __expf(Co - (aLo + aHi));
                float eB = __expf(Co - (bLo + bHi));
                float sA = eA, sB = eB;
                #pragma unroll
                for (int off = 16; off; off >>= 1) {
                    sA += __shfl_xor_sync(0xffffffffu, sA, off);
                    sB += __shfl_xor_sync(0xffffffffu, sB, off);
                }
                float rA = __fdividef(eA, sA) * ckA;  // exact r*a, o-normalized
                float rB = __fdividef(eB, sB) * ckB;
                sR[ka*32 + lane] = rA;
                sR[kb*32 + lane] = rB;
                racc += rA + rB;
            }
            atomicAdd(&rs[lane], racc);
        }
        __syncthreads();
    }

    // ---- output: [n, 544] = concat(mean[32*16], act[32]) ----
    {
        int o = tid >> 4, s = tid & 15;
        out[(size_t)n*544 + tid] = sMean[o*17 + s];
        if (tid < 32)
            out[(size_t)n*544 + 512 + tid] = sAct[tid];
    }
}

extern "C" void kernel_launch(void* const* d_in, const int* in_sizes, int n_in,
                              void* d_out, int out_size)
{
    const float* x  = (const float*)d_in[0];
    const float* w  = (const float*)d_in[1];
    const float* bu = (const float*)d_in[2];
    const float* ba = (const float*)d_in[3];
    float* out = (float*)d_out;

    // 80 KB request pins occupancy at exactly 2 CTAs/SM (L2-resident vote wave)
    const int smem_bytes = 81920;
    cudaFuncSetAttribute(convcaps_kernel,
                         cudaFuncAttributeMaxDynamicSharedMemorySize, smem_bytes);
    convcaps_kernel<<<NPOS, NT, smem_bytes>>>(x, w, bu, ba, out);
}